// round 2
// baseline (speedup 1.0000x reference)
#include <cuda_runtime.h>
#include <math.h>

#define IMG_H 800.0f
#define IMG_W 1280.0f
#define FSCALE (1.0f/16.0f)
#define PP 14
#define NUM_CLASSES 80
#define SCORE_TH 0.05f
#define NMS_TH 0.5f
#define MAX_DET 100
#define IOU_TH 0.5f
#define SCALE_CLAMP 4.135166556742356f
#define FH 50
#define FW 80
#define FC 1024
#define NIMG 2
#define NR 256
#define NGT 64

// Scratch (device globals; no allocation allowed)
__device__ float g_featvec[NIMG * NR * FC];
__device__ float g_boxes[NIMG * NR * 4];
__device__ float g_scores[NIMG * NR];

// ---------------------------------------------------------------------------
// Kernel 1: proposal<->gt matching. grid(2), block(256). One thread = proposal.
// ---------------------------------------------------------------------------
__global__ void match_kernel(const float* __restrict__ gt,
                             const float* __restrict__ prop,
                             float* __restrict__ out_idx,
                             float* __restrict__ out_lbl) {
    int n = blockIdx.x;
    int r = threadIdx.x;
    const float* p = prop + (n * NR + r) * 4;
    float px1 = p[0], py1 = p[1], px2 = p[2], py2 = p[3];
    float pa = (px2 - px1) * (py2 - py1);
    float best = -1.0f;
    int bi = 0;
    for (int g = 0; g < NGT; g++) {
        const float* gb = gt + (n * NGT + g) * 4;
        float gx1 = gb[0], gy1 = gb[1], gx2 = gb[2], gy2 = gb[3];
        float ga = (gx2 - gx1) * (gy2 - gy1);
        float lx = fmaxf(gx1, px1), ly = fmaxf(gy1, py1);
        float rx = fminf(gx2, px2), ry = fminf(gy2, py2);
        float w = fmaxf(rx - lx, 0.0f), h = fmaxf(ry - ly, 0.0f);
        float inter = w * h;
        float iou = inter / fmaxf(ga + pa - inter, 1e-9f);
        if (iou > best) { best = iou; bi = g; }
    }
    out_idx[n * NR + r] = (float)bi;
    out_lbl[n * NR + r] = (best >= IOU_TH) ? 1.0f : 0.0f;
}

// ---------------------------------------------------------------------------
// Kernel 2: Separable ROIAlign (P=14, S=1) + average pool -> feat_vec.
// mean over 14x14 bilinear samples = (1/196) * sum_{y,x} wy[y]*wx[x]*f[y,x]
// where wy[y] = sum_py (bilinear y-weight), wx likewise (weights separable,
// bin sums independent). Each feature cell in the footprint is loaded ONCE
// per channel instead of up to 4*196 times.
// grid(256, 2) = (box, image), block(256): thread t owns channels [4t,4t+4).
// ---------------------------------------------------------------------------
__global__ void roi_kernel(const float* __restrict__ feat,
                           const float* __restrict__ prop,
                           float* __restrict__ featvec) {
    int r = blockIdx.x;
    int n = blockIdx.y;
    int t = threadIdx.x;

    __shared__ float swy[FH], swx[FW];
    __shared__ int sylo, syhi, sxlo, sxhi;

    if (t < FH) swy[t] = 0.0f;
    if (t < FW) swx[t] = 0.0f;
    __syncthreads();

    const float* p = prop + (n * NR + r) * 4;

    if (t == 0) {
        float y1 = p[1] * FSCALE, y2 = p[3] * FSCALE;
        float bh = (y2 - y1) * (1.0f / (float)PP);
        int lo = FH, hi = 0;
        for (int py = 0; py < PP; py++) {
            float gy = y1 + ((float)py + 0.5f) * bh - 0.5f;
            gy = fminf(fmaxf(gy, 0.0f), (float)(FH - 1));
            float y0 = floorf(gy);
            int y0i = (int)y0;
            int y1i = min(y0i + 1, FH - 1);
            float ly = gy - y0;
            swy[y0i] += 1.0f - ly;
            swy[y1i] += ly;
            lo = min(lo, y0i);
            hi = max(hi, y1i);
        }
        sylo = lo; syhi = hi;
    } else if (t == 32) {
        float x1 = p[0] * FSCALE, x2 = p[2] * FSCALE;
        float bw = (x2 - x1) * (1.0f / (float)PP);
        int lo = FW, hi = 0;
        for (int px = 0; px < PP; px++) {
            float gx = x1 + ((float)px + 0.5f) * bw - 0.5f;
            gx = fminf(fmaxf(gx, 0.0f), (float)(FW - 1));
            float x0 = floorf(gx);
            int x0i = (int)x0;
            int x1i = min(x0i + 1, FW - 1);
            float lx = gx - x0;
            swx[x0i] += 1.0f - lx;
            swx[x1i] += lx;
            lo = min(lo, x0i);
            hi = max(hi, x1i);
        }
        sxlo = lo; sxhi = hi;
    }
    __syncthreads();

    int ylo = sylo, yhi = syhi, xlo = sxlo, xhi = sxhi;
    const float4* f = (const float4*)(feat + (size_t)n * FH * FW * FC);
    float4 acc = make_float4(0.f, 0.f, 0.f, 0.f);

    for (int y = ylo; y <= yhi; y++) {
        float wyv = swy[y];
        const float4* row = f + (size_t)(y * FW) * (FC / 4) + t;
        for (int x = xlo; x <= xhi; x++) {
            float w = wyv * swx[x];
            float4 v = row[(size_t)x * (FC / 4)];
            acc.x += w * v.x;
            acc.y += w * v.y;
            acc.z += w * v.z;
            acc.w += w * v.w;
        }
    }
    float inv = 1.0f / (float)(PP * PP);
    acc.x *= inv; acc.y *= inv; acc.z *= inv; acc.w *= inv;
    ((float4*)featvec)[(size_t)(n * NR + r) * (FC / 4) + t] = acc;
}

// ---------------------------------------------------------------------------
// Kernel 3: heads. grid(512) one block per proposal, block(96).
// Threads 0..80 compute cls logits (coalesced W_cls columns), threads 84..87
// compute box deltas. Thread 0 does softmax + decode.
// ---------------------------------------------------------------------------
__global__ void head_kernel(const float* __restrict__ featvec,
                            const float* __restrict__ prop,
                            const float* __restrict__ Wc,
                            const float* __restrict__ bc,
                            const float* __restrict__ Wb,
                            const float* __restrict__ bb,
                            float* __restrict__ boxes,
                            float* __restrict__ scores) {
    int gid = blockIdx.x;   // n*256 + r
    int t = threadIdx.x;
    __shared__ float sf[FC];
    __shared__ float slog[NUM_CLASSES + 1];
    __shared__ float sdel[4];

    const float* fv = featvec + (size_t)gid * FC;
    for (int i = t; i < FC; i += blockDim.x) sf[i] = fv[i];
    __syncthreads();

    if (t < NUM_CLASSES + 1) {
        float acc = bc[t];
        #pragma unroll 8
        for (int k = 0; k < FC; k++) acc += sf[k] * Wc[k * (NUM_CLASSES + 1) + t];
        slog[t] = acc;
    } else if (t >= 84 && t < 88) {
        int c = t - 84;
        float acc = bb[c];
        #pragma unroll 8
        for (int k = 0; k < FC; k++) acc += sf[k] * Wb[k * 4 + c];
        sdel[c] = acc;
    }
    __syncthreads();

    if (t == 0) {
        float m = -INFINITY;
        for (int c = 0; c <= NUM_CLASSES; c++) m = fmaxf(m, slog[c]);
        float s = 0.0f;
        float fg = -INFINITY;
        for (int c = 0; c <= NUM_CLASSES; c++) {
            float e = expf(slog[c] - m);
            s += e;
            if (c < NUM_CLASSES) fg = fmaxf(fg, e);
        }
        scores[gid] = fg / s;

        const float* p = prop + (size_t)gid * 4;
        float px1 = p[0], py1 = p[1], px2 = p[2], py2 = p[3];
        float wdt = px2 - px1, hgt = py2 - py1;
        float cx = px1 + 0.5f * wdt, cy = py1 + 0.5f * hgt;
        float dx = sdel[0] * 0.1f;
        float dy = sdel[1] * 0.1f;
        float dw = fminf(sdel[2] * 0.2f, SCALE_CLAMP);
        float dh = fminf(sdel[3] * 0.2f, SCALE_CLAMP);
        float pcx = dx * wdt + cx;
        float pcy = dy * hgt + cy;
        float pw = expf(dw) * wdt;
        float ph = expf(dh) * hgt;
        float ox1 = fminf(fmaxf(pcx - 0.5f * pw, 0.0f), IMG_W);
        float oy1 = fminf(fmaxf(pcy - 0.5f * ph, 0.0f), IMG_H);
        float ox2 = fminf(fmaxf(pcx + 0.5f * pw, 0.0f), IMG_W);
        float oy2 = fminf(fmaxf(pcy + 0.5f * ph, 0.0f), IMG_H);
        float* ob = boxes + (size_t)gid * 4;
        ob[0] = ox1; ob[1] = oy1; ob[2] = ox2; ob[3] = oy2;
    }
}

// ---------------------------------------------------------------------------
// Kernel 4: NMS + ranking + det write. grid(2) one block per image, block(256).
// Stable descending rank, 256x256 IoU bitmatrix (float4 shared reads), then a
// WARP-PARALLEL greedy scan: lane w<8 checks word w of supmask[i] & keptw,
// one __any_sync per candidate. keptw only holds bits j<i when candidate i is
// processed, so no masking is needed.
// ---------------------------------------------------------------------------
__global__ void nms_kernel(const float* __restrict__ boxes,
                           const float* __restrict__ scores,
                           float* __restrict__ det) {
    int n = blockIdx.x;
    int t = threadIdx.x;

    __shared__ float ss[NR];
    __shared__ int order[NR];
    __shared__ float4 sb[NR];
    __shared__ unsigned int supmask[NR][8];
    __shared__ unsigned int keptw[8];
    __shared__ float smask[NR];

    float s_i = scores[n * NR + t];
    ss[t] = s_i;
    if (t < 8) keptw[t] = 0u;
    __syncthreads();

    // stable descending rank of this proposal
    int rk = 0;
    for (int j = 0; j < NR; j++) {
        float sj = ss[j];
        rk += (sj > s_i) || (sj == s_i && j < t);
    }
    order[rk] = t;
    __syncthreads();

    // gather sorted boxes
    sb[t] = ((const float4*)boxes)[n * NR + order[t]];
    __syncthreads();

    // IoU bitmatrix row t (sorted order)
    {
        float4 a = sb[t];
        float aa = (a.z - a.x) * (a.w - a.y);
        #pragma unroll
        for (int w = 0; w < 8; w++) {
            unsigned int word = 0;
            for (int k = 0; k < 32; k++) {
                float4 b = sb[w * 32 + k];
                float ba = (b.z - b.x) * (b.w - b.y);
                float lx = fmaxf(a.x, b.x), ly = fmaxf(a.y, b.y);
                float rx = fminf(a.z, b.z), ry = fminf(a.w, b.w);
                float ww = fmaxf(rx - lx, 0.0f), hh = fmaxf(ry - ly, 0.0f);
                float inter = ww * hh;
                float iou = inter / fmaxf(aa + ba - inter, 1e-9f);
                if (iou > NMS_TH) word |= (1u << k);
            }
            supmask[t][w] = word;
        }
    }
    __syncthreads();

    // warp-parallel greedy over sorted candidates
    if (t < 32) {
        for (int i = 0; i < NR; i++) {
            unsigned int m = 0;
            if (t < 8) m = supmask[i][t] & keptw[t];
            bool sup = __any_sync(0xffffffffu, m != 0u);
            if (!sup && t == (i >> 5)) keptw[t] |= (1u << (i & 31));
        }
    }
    __syncthreads();

    // keep for original index t (its sorted position is rk)
    bool kp = (keptw[rk >> 5] >> (rk & 31)) & 1u;
    kp = kp && (s_i > SCORE_TH);
    smask[t] = kp ? s_i : -INFINITY;
    __syncthreads();

    int rank2 = 0;
    float mi = smask[t];
    for (int j = 0; j < NR; j++) {
        float mj = smask[j];
        rank2 += (mj > mi) || (mj == mi && j < t);
    }
    kp = kp && (rank2 < MAX_DET);

    const float* bsrc = boxes + (size_t)(n * NR + t) * 4;
    float* drow = det + (size_t)(n * NR + t) * 6;
    drow[0] = bsrc[0]; drow[1] = bsrc[1];
    drow[2] = bsrc[2]; drow[3] = bsrc[3];
    drow[4] = s_i;
    drow[5] = kp ? 1.0f : 0.0f;
}

// ---------------------------------------------------------------------------
extern "C" void kernel_launch(void* const* d_in, const int* in_sizes, int n_in,
                              void* d_out, int out_size) {
    const float* features = (const float*)d_in[0];
    const float* proposals = (const float*)d_in[1];
    const float* gt_boxes = (const float*)d_in[2];
    // d_in[3] = gt_classes (unused by reference)
    const float* W_cls = (const float*)d_in[4];
    const float* b_cls = (const float*)d_in[5];
    const float* W_box = (const float*)d_in[6];
    const float* b_box = (const float*)d_in[7];

    float* out = (float*)d_out;
    float* det = out;                          // 2*256*6 = 3072
    float* out_idx = out + NIMG * NR * 6;      // 2*256   = 512
    float* out_lbl = out_idx + NIMG * NR;      // 2*256   = 512

    float* featvec; cudaGetSymbolAddress((void**)&featvec, g_featvec);
    float* boxes;   cudaGetSymbolAddress((void**)&boxes, g_boxes);
    float* scores;  cudaGetSymbolAddress((void**)&scores, g_scores);

    match_kernel<<<NIMG, NR>>>(gt_boxes, proposals, out_idx, out_lbl);
    roi_kernel<<<dim3(NR, NIMG), 256>>>(features, proposals, featvec);
    head_kernel<<<NIMG * NR, 96>>>(featvec, proposals, W_cls, b_cls, W_box,
                                   b_box, boxes, scores);
    nms_kernel<<<NIMG, NR>>>(boxes, scores, det);
}

// round 3
// speedup vs baseline: 1.0089x; 1.0089x over previous
#include <cuda_runtime.h>
#include <math.h>

#define IMG_H 800.0f
#define IMG_W 1280.0f
#define FSCALE (1.0f/16.0f)
#define PP 14
#define NUM_CLASSES 80
#define SCORE_TH 0.05f
#define NMS_TH 0.5f
#define MAX_DET 100
#define IOU_TH 0.5f
#define SCALE_CLAMP 4.135166556742356f
#define FH 50
#define FW 80
#define FC 1024
#define NIMG 2
#define NR 256
#define NGT 64

// Scratch (device globals; no allocation allowed)
__device__ float g_featvec[NIMG * NR * FC];
__device__ float g_boxes[NIMG * NR * 4];
__device__ float g_scores[NIMG * NR];

// ---------------------------------------------------------------------------
// Kernel 1: proposal<->gt matching. grid(2), block(256). One thread = proposal.
// ---------------------------------------------------------------------------
__global__ void match_kernel(const float* __restrict__ gt,
                             const float* __restrict__ prop,
                             float* __restrict__ out_idx,
                             float* __restrict__ out_lbl) {
    int n = blockIdx.x;
    int r = threadIdx.x;
    const float* p = prop + (n * NR + r) * 4;
    float px1 = p[0], py1 = p[1], px2 = p[2], py2 = p[3];
    float pa = (px2 - px1) * (py2 - py1);
    float best = -1.0f;
    int bi = 0;
    for (int g = 0; g < NGT; g++) {
        const float* gb = gt + (n * NGT + g) * 4;
        float gx1 = gb[0], gy1 = gb[1], gx2 = gb[2], gy2 = gb[3];
        float ga = (gx2 - gx1) * (gy2 - gy1);
        float lx = fmaxf(gx1, px1), ly = fmaxf(gy1, py1);
        float rx = fminf(gx2, px2), ry = fminf(gy2, py2);
        float w = fmaxf(rx - lx, 0.0f), h = fmaxf(ry - ly, 0.0f);
        float inter = w * h;
        float iou = inter / fmaxf(ga + pa - inter, 1e-9f);
        if (iou > best) { best = iou; bi = g; }
    }
    out_idx[n * NR + r] = (float)bi;
    out_lbl[n * NR + r] = (best >= IOU_TH) ? 1.0f : 0.0f;
}

// ---------------------------------------------------------------------------
// Kernel 2: Separable ROIAlign (P=14, S=1) + average pool -> feat_vec.
// mean over 14x14 bilinear samples = (1/196) * sum_{y,x} wy[y]*wx[x]*f[y,x]
// where wy[y] = sum_py (bilinear y-weight), wx likewise (weights separable,
// bin sums independent). Each feature cell in the footprint is loaded ONCE
// per channel instead of up to 4*196 times.
// grid(256, 2) = (box, image), block(256): thread t owns channels [4t,4t+4).
// ---------------------------------------------------------------------------
__global__ void roi_kernel(const float* __restrict__ feat,
                           const float* __restrict__ prop,
                           float* __restrict__ featvec) {
    int r = blockIdx.x;
    int n = blockIdx.y;
    int t = threadIdx.x;

    __shared__ float swy[FH], swx[FW];
    __shared__ int sylo, syhi, sxlo, sxhi;

    if (t < FH) swy[t] = 0.0f;
    if (t < FW) swx[t] = 0.0f;
    __syncthreads();

    const float* p = prop + (n * NR + r) * 4;

    if (t == 0) {
        float y1 = p[1] * FSCALE, y2 = p[3] * FSCALE;
        float bh = (y2 - y1) * (1.0f / (float)PP);
        int lo = FH, hi = 0;
        for (int py = 0; py < PP; py++) {
            float gy = y1 + ((float)py + 0.5f) * bh - 0.5f;
            gy = fminf(fmaxf(gy, 0.0f), (float)(FH - 1));
            float y0 = floorf(gy);
            int y0i = (int)y0;
            int y1i = min(y0i + 1, FH - 1);
            float ly = gy - y0;
            swy[y0i] += 1.0f - ly;
            swy[y1i] += ly;
            lo = min(lo, y0i);
            hi = max(hi, y1i);
        }
        sylo = lo; syhi = hi;
    } else if (t == 32) {
        float x1 = p[0] * FSCALE, x2 = p[2] * FSCALE;
        float bw = (x2 - x1) * (1.0f / (float)PP);
        int lo = FW, hi = 0;
        for (int px = 0; px < PP; px++) {
            float gx = x1 + ((float)px + 0.5f) * bw - 0.5f;
            gx = fminf(fmaxf(gx, 0.0f), (float)(FW - 1));
            float x0 = floorf(gx);
            int x0i = (int)x0;
            int x1i = min(x0i + 1, FW - 1);
            float lx = gx - x0;
            swx[x0i] += 1.0f - lx;
            swx[x1i] += lx;
            lo = min(lo, x0i);
            hi = max(hi, x1i);
        }
        sxlo = lo; sxhi = hi;
    }
    __syncthreads();

    int ylo = sylo, yhi = syhi, xlo = sxlo, xhi = sxhi;
    const float4* f = (const float4*)(feat + (size_t)n * FH * FW * FC);
    float4 acc = make_float4(0.f, 0.f, 0.f, 0.f);

    for (int y = ylo; y <= yhi; y++) {
        float wyv = swy[y];
        const float4* row = f + (size_t)(y * FW) * (FC / 4) + t;
        for (int x = xlo; x <= xhi; x++) {
            float w = wyv * swx[x];
            float4 v = row[(size_t)x * (FC / 4)];
            acc.x += w * v.x;
            acc.y += w * v.y;
            acc.z += w * v.z;
            acc.w += w * v.w;
        }
    }
    float inv = 1.0f / (float)(PP * PP);
    acc.x *= inv; acc.y *= inv; acc.z *= inv; acc.w *= inv;
    ((float4*)featvec)[(size_t)(n * NR + r) * (FC / 4) + t] = acc;
}

// ---------------------------------------------------------------------------
// Kernel 3: heads. grid(512) one block per proposal, block(96).
// Threads 0..80 compute cls logits (coalesced W_cls columns), threads 84..87
// compute box deltas. Thread 0 does softmax + decode.
// ---------------------------------------------------------------------------
__global__ void head_kernel(const float* __restrict__ featvec,
                            const float* __restrict__ prop,
                            const float* __restrict__ Wc,
                            const float* __restrict__ bc,
                            const float* __restrict__ Wb,
                            const float* __restrict__ bb,
                            float* __restrict__ boxes,
                            float* __restrict__ scores) {
    int gid = blockIdx.x;   // n*256 + r
    int t = threadIdx.x;
    __shared__ float sf[FC];
    __shared__ float slog[NUM_CLASSES + 1];
    __shared__ float sdel[4];

    const float* fv = featvec + (size_t)gid * FC;
    for (int i = t; i < FC; i += blockDim.x) sf[i] = fv[i];
    __syncthreads();

    if (t < NUM_CLASSES + 1) {
        float acc = bc[t];
        #pragma unroll 8
        for (int k = 0; k < FC; k++) acc += sf[k] * Wc[k * (NUM_CLASSES + 1) + t];
        slog[t] = acc;
    } else if (t >= 84 && t < 88) {
        int c = t - 84;
        float acc = bb[c];
        #pragma unroll 8
        for (int k = 0; k < FC; k++) acc += sf[k] * Wb[k * 4 + c];
        sdel[c] = acc;
    }
    __syncthreads();

    if (t == 0) {
        float m = -INFINITY;
        for (int c = 0; c <= NUM_CLASSES; c++) m = fmaxf(m, slog[c]);
        float s = 0.0f;
        float fg = -INFINITY;
        for (int c = 0; c <= NUM_CLASSES; c++) {
            float e = expf(slog[c] - m);
            s += e;
            if (c < NUM_CLASSES) fg = fmaxf(fg, e);
        }
        scores[gid] = fg / s;

        const float* p = prop + (size_t)gid * 4;
        float px1 = p[0], py1 = p[1], px2 = p[2], py2 = p[3];
        float wdt = px2 - px1, hgt = py2 - py1;
        float cx = px1 + 0.5f * wdt, cy = py1 + 0.5f * hgt;
        float dx = sdel[0] * 0.1f;
        float dy = sdel[1] * 0.1f;
        float dw = fminf(sdel[2] * 0.2f, SCALE_CLAMP);
        float dh = fminf(sdel[3] * 0.2f, SCALE_CLAMP);
        float pcx = dx * wdt + cx;
        float pcy = dy * hgt + cy;
        float pw = expf(dw) * wdt;
        float ph = expf(dh) * hgt;
        float ox1 = fminf(fmaxf(pcx - 0.5f * pw, 0.0f), IMG_W);
        float oy1 = fminf(fmaxf(pcy - 0.5f * ph, 0.0f), IMG_H);
        float ox2 = fminf(fmaxf(pcx + 0.5f * pw, 0.0f), IMG_W);
        float oy2 = fminf(fmaxf(pcy + 0.5f * ph, 0.0f), IMG_H);
        float* ob = boxes + (size_t)gid * 4;
        ob[0] = ox1; ob[1] = oy1; ob[2] = ox2; ob[3] = oy2;
    }
}

// ---------------------------------------------------------------------------
// Kernel 4: NMS + ranking + det write. grid(2) one block per image, block(256).
// Stable descending rank, 256x256 IoU bitmatrix (float4 shared reads), then a
// WARP-PARALLEL greedy scan: lane w<8 checks word w of supmask[i] & keptw,
// one __any_sync per candidate. keptw only holds bits j<i when candidate i is
// processed, so no masking is needed.
// ---------------------------------------------------------------------------
__global__ void nms_kernel(const float* __restrict__ boxes,
                           const float* __restrict__ scores,
                           float* __restrict__ det) {
    int n = blockIdx.x;
    int t = threadIdx.x;

    __shared__ float ss[NR];
    __shared__ int order[NR];
    __shared__ float4 sb[NR];
    __shared__ unsigned int supmask[NR][8];
    __shared__ unsigned int keptw[8];
    __shared__ float smask[NR];

    float s_i = scores[n * NR + t];
    ss[t] = s_i;
    if (t < 8) keptw[t] = 0u;
    __syncthreads();

    // stable descending rank of this proposal
    int rk = 0;
    for (int j = 0; j < NR; j++) {
        float sj = ss[j];
        rk += (sj > s_i) || (sj == s_i && j < t);
    }
    order[rk] = t;
    __syncthreads();

    // gather sorted boxes
    sb[t] = ((const float4*)boxes)[n * NR + order[t]];
    __syncthreads();

    // IoU bitmatrix row t (sorted order)
    {
        float4 a = sb[t];
        float aa = (a.z - a.x) * (a.w - a.y);
        #pragma unroll
        for (int w = 0; w < 8; w++) {
            unsigned int word = 0;
            for (int k = 0; k < 32; k++) {
                float4 b = sb[w * 32 + k];
                float ba = (b.z - b.x) * (b.w - b.y);
                float lx = fmaxf(a.x, b.x), ly = fmaxf(a.y, b.y);
                float rx = fminf(a.z, b.z), ry = fminf(a.w, b.w);
                float ww = fmaxf(rx - lx, 0.0f), hh = fmaxf(ry - ly, 0.0f);
                float inter = ww * hh;
                float iou = inter / fmaxf(aa + ba - inter, 1e-9f);
                if (iou > NMS_TH) word |= (1u << k);
            }
            supmask[t][w] = word;
        }
    }
    __syncthreads();

    // warp-parallel greedy over sorted candidates
    if (t < 32) {
        for (int i = 0; i < NR; i++) {
            unsigned int m = 0;
            if (t < 8) m = supmask[i][t] & keptw[t];
            bool sup = __any_sync(0xffffffffu, m != 0u);
            if (!sup && t == (i >> 5)) keptw[t] |= (1u << (i & 31));
        }
    }
    __syncthreads();

    // keep for original index t (its sorted position is rk)
    bool kp = (keptw[rk >> 5] >> (rk & 31)) & 1u;
    kp = kp && (s_i > SCORE_TH);
    smask[t] = kp ? s_i : -INFINITY;
    __syncthreads();

    int rank2 = 0;
    float mi = smask[t];
    for (int j = 0; j < NR; j++) {
        float mj = smask[j];
        rank2 += (mj > mi) || (mj == mi && j < t);
    }
    kp = kp && (rank2 < MAX_DET);

    const float* bsrc = boxes + (size_t)(n * NR + t) * 4;
    float* drow = det + (size_t)(n * NR + t) * 6;
    drow[0] = bsrc[0]; drow[1] = bsrc[1];
    drow[2] = bsrc[2]; drow[3] = bsrc[3];
    drow[4] = s_i;
    drow[5] = kp ? 1.0f : 0.0f;
}

// ---------------------------------------------------------------------------
extern "C" void kernel_launch(void* const* d_in, const int* in_sizes, int n_in,
                              void* d_out, int out_size) {
    const float* features = (const float*)d_in[0];
    const float* proposals = (const float*)d_in[1];
    const float* gt_boxes = (const float*)d_in[2];
    // d_in[3] = gt_classes (unused by reference)
    const float* W_cls = (const float*)d_in[4];
    const float* b_cls = (const float*)d_in[5];
    const float* W_box = (const float*)d_in[6];
    const float* b_box = (const float*)d_in[7];

    float* out = (float*)d_out;
    float* det = out;                          // 2*256*6 = 3072
    float* out_idx = out + NIMG * NR * 6;      // 2*256   = 512
    float* out_lbl = out_idx + NIMG * NR;      // 2*256   = 512

    float* featvec; cudaGetSymbolAddress((void**)&featvec, g_featvec);
    float* boxes;   cudaGetSymbolAddress((void**)&boxes, g_boxes);
    float* scores;  cudaGetSymbolAddress((void**)&scores, g_scores);

    match_kernel<<<NIMG, NR>>>(gt_boxes, proposals, out_idx, out_lbl);
    roi_kernel<<<dim3(NR, NIMG), 256>>>(features, proposals, featvec);
    head_kernel<<<NIMG * NR, 96>>>(featvec, proposals, W_cls, b_cls, W_box,
                                   b_box, boxes, scores);
    nms_kernel<<<NIMG, NR>>>(boxes, scores, det);
}

// round 4
// speedup vs baseline: 1.2084x; 1.1977x over previous
#include <cuda_runtime.h>
#include <math.h>

#define IMG_H 800.0f
#define IMG_W 1280.0f
#define FSCALE (1.0f/16.0f)
#define PP 14
#define NUM_CLASSES 80
#define SCORE_TH 0.05f
#define NMS_TH 0.5f
#define MAX_DET 100
#define IOU_TH 0.5f
#define SCALE_CLAMP 4.135166556742356f
#define FH 50
#define FW 80
#define FC 1024
#define NIMG 2
#define NR 256
#define NGT 64

// Scratch (device globals; no allocation allowed)
__device__ float g_featvec[NIMG * NR * FC];
__device__ float g_boxes[NIMG * NR * 4];
__device__ float g_scores[NIMG * NR];
__device__ float g_wy[NIMG * NR * FH];
__device__ float g_wx[NIMG * NR * FW];
__device__ int   g_bnd[NIMG * NR * 4];   // ylo,yhi,xlo,xhi

// ---------------------------------------------------------------------------
// Kernel 1: proposal<->gt matching. grid(2), block(256).
// ---------------------------------------------------------------------------
__global__ void match_kernel(const float* __restrict__ gt,
                             const float* __restrict__ prop,
                             float* __restrict__ out_idx,
                             float* __restrict__ out_lbl) {
    int n = blockIdx.x;
    int r = threadIdx.x;
    const float* p = prop + (n * NR + r) * 4;
    float px1 = p[0], py1 = p[1], px2 = p[2], py2 = p[3];
    float pa = (px2 - px1) * (py2 - py1);
    float best = -1.0f;
    int bi = 0;
    for (int g = 0; g < NGT; g++) {
        const float* gb = gt + (n * NGT + g) * 4;
        float gx1 = gb[0], gy1 = gb[1], gx2 = gb[2], gy2 = gb[3];
        float ga = (gx2 - gx1) * (gy2 - gy1);
        float lx = fmaxf(gx1, px1), ly = fmaxf(gy1, py1);
        float rx = fminf(gx2, px2), ry = fminf(gy2, py2);
        float w = fmaxf(rx - lx, 0.0f), h = fmaxf(ry - ly, 0.0f);
        float inter = w * h;
        float iou = inter / fmaxf(ga + pa - inter, 1e-9f);
        if (iou > best) { best = iou; bi = g; }
    }
    out_idx[n * NR + r] = (float)bi;
    out_lbl[n * NR + r] = (best >= IOU_TH) ? 1.0f : 0.0f;
}

// ---------------------------------------------------------------------------
// Kernel 1b: separable ROIAlign weight tables per box -> global.
// grid(8, 2): 32 boxes per block, block(256). Within each box: sub-thread 0
// builds the y table, sub-thread 1 the x table (14 serial scatter-adds each).
// ---------------------------------------------------------------------------
__global__ void weight_kernel(const float* __restrict__ prop) {
    int n = blockIdx.y;
    int b0 = blockIdx.x * 32;
    int t = threadIdx.x;

    __shared__ float wy[32 * FH];
    __shared__ float wx[32 * FW];

    for (int i = t; i < 32 * FH; i += 256) wy[i] = 0.0f;
    for (int i = t; i < 32 * FW; i += 256) wx[i] = 0.0f;
    __syncthreads();

    int b = t >> 3;          // box within block
    int sub = t & 7;
    int box = b0 + b;
    const float* p = prop + (n * NR + box) * 4;

    if (sub == 0) {
        float y1 = p[1] * FSCALE, y2 = p[3] * FSCALE;
        float bh = (y2 - y1) * (1.0f / (float)PP);
        int lo = FH, hi = 0;
        for (int py = 0; py < PP; py++) {
            float gy = y1 + ((float)py + 0.5f) * bh - 0.5f;
            gy = fminf(fmaxf(gy, 0.0f), (float)(FH - 1));
            float y0 = floorf(gy);
            int y0i = (int)y0;
            int y1i = min(y0i + 1, FH - 1);
            float ly = gy - y0;
            wy[b * FH + y0i] += 1.0f - ly;
            wy[b * FH + y1i] += ly;
            lo = min(lo, y0i);
            hi = max(hi, y1i);
        }
        g_bnd[(n * NR + box) * 4 + 0] = lo;
        g_bnd[(n * NR + box) * 4 + 1] = hi;
    } else if (sub == 1) {
        float x1 = p[0] * FSCALE, x2 = p[2] * FSCALE;
        float bw = (x2 - x1) * (1.0f / (float)PP);
        int lo = FW, hi = 0;
        for (int px = 0; px < PP; px++) {
            float gx = x1 + ((float)px + 0.5f) * bw - 0.5f;
            gx = fminf(fmaxf(gx, 0.0f), (float)(FW - 1));
            float x0 = floorf(gx);
            int x0i = (int)x0;
            int x1i = min(x0i + 1, FW - 1);
            float lx = gx - x0;
            wx[b * FW + x0i] += 1.0f - lx;
            wx[b * FW + x1i] += lx;
            lo = min(lo, x0i);
            hi = max(hi, x1i);
        }
        g_bnd[(n * NR + box) * 4 + 2] = lo;
        g_bnd[(n * NR + box) * 4 + 3] = hi;
    }
    __syncthreads();

    // flat coalesced copy to global (boxes contiguous)
    for (int i = t; i < 32 * FH; i += 256) g_wy[(n * NR + b0) * FH + i] = wy[i];
    for (int i = t; i < 32 * FW; i += 256) g_wx[(n * NR + b0) * FW + i] = wx[i];
}

// ---------------------------------------------------------------------------
// Kernel 2: ROIAlign via shared feature slice.
// grid(FC/8=128, 2) = (channel-chunk, image), block(256), dyn smem 125KB.
// Block loads its 50x80x8 slice ONCE (global feature traffic = 33MB total),
// then thread t = box t accumulates its weighted footprint from smem.
// ---------------------------------------------------------------------------
__global__ void roi_kernel(const float* __restrict__ feat,
                           float* __restrict__ featvec) {
    extern __shared__ float sl[];           // [FH*FW][8]
    int c0 = blockIdx.x * 8;
    int n = blockIdx.y;
    int t = threadIdx.x;

    const float* fbase = feat + (size_t)n * FH * FW * FC + c0;
    for (int idx = t; idx < FH * FW; idx += 256) {
        const float4* src = (const float4*)(fbase + (size_t)idx * FC);
        float4 a = src[0];
        float4 b = src[1];
        float4* dst = (float4*)(sl + idx * 8);
        dst[0] = a;
        dst[1] = b;
    }
    __syncthreads();

    int box = t;
    const int4 bnd = *(const int4*)&g_bnd[(n * NR + box) * 4];
    int ylo = bnd.x, yhi = bnd.y, xlo = bnd.z, xhi = bnd.w;
    const float* wyp = &g_wy[(n * NR + box) * FH];
    const float* wxp = &g_wx[(n * NR + box) * FW];

    float4 acc0 = make_float4(0.f, 0.f, 0.f, 0.f);
    float4 acc1 = make_float4(0.f, 0.f, 0.f, 0.f);

    for (int y = ylo; y <= yhi; y++) {
        float wyv = wyp[y];
        const float* rowp = sl + (y * FW) * 8;
        for (int x = xlo; x <= xhi; x++) {
            float w = wyv * wxp[x];
            const float4* cell = (const float4*)(rowp + x * 8);
            float4 v0 = cell[0];
            float4 v1 = cell[1];
            acc0.x += w * v0.x; acc0.y += w * v0.y;
            acc0.z += w * v0.z; acc0.w += w * v0.w;
            acc1.x += w * v1.x; acc1.y += w * v1.y;
            acc1.z += w * v1.z; acc1.w += w * v1.w;
        }
    }
    const float inv = 1.0f / (float)(PP * PP);
    acc0.x *= inv; acc0.y *= inv; acc0.z *= inv; acc0.w *= inv;
    acc1.x *= inv; acc1.y *= inv; acc1.z *= inv; acc1.w *= inv;
    float4* out = (float4*)(featvec + (size_t)(n * NR + box) * FC + c0);
    out[0] = acc0;
    out[1] = acc1;
}

// ---------------------------------------------------------------------------
// Kernel 3: heads. grid(128): 4 proposals per block, block(128).
// Thread t<81 owns cls column t with 4 accumulators (4 FMA per W_cls load);
// threads 96..99 own box delta columns. Threads 0..3 do softmax + decode.
// ---------------------------------------------------------------------------
__global__ void head_kernel(const float* __restrict__ featvec,
                            const float* __restrict__ prop,
                            const float* __restrict__ Wc,
                            const float* __restrict__ bc,
                            const float* __restrict__ Wb,
                            const float* __restrict__ bb,
                            float* __restrict__ boxes,
                            float* __restrict__ scores) {
    int p0 = blockIdx.x * 4;
    int t = threadIdx.x;
    __shared__ float sf[4][FC];
    __shared__ float slog[4][NUM_CLASSES + 1];
    __shared__ float sdel[4][4];

    const float* fv = featvec + (size_t)p0 * FC;
    for (int i = t; i < 4 * FC; i += 128) sf[i >> 10][i & (FC - 1)] = fv[i];
    __syncthreads();

    if (t < NUM_CLASSES + 1) {
        float a0 = 0.f, a1 = 0.f, a2 = 0.f, a3 = 0.f;
        #pragma unroll 4
        for (int k = 0; k < FC; k++) {
            float w = Wc[k * (NUM_CLASSES + 1) + t];
            a0 += sf[0][k] * w;
            a1 += sf[1][k] * w;
            a2 += sf[2][k] * w;
            a3 += sf[3][k] * w;
        }
        float bv = bc[t];
        slog[0][t] = a0 + bv;
        slog[1][t] = a1 + bv;
        slog[2][t] = a2 + bv;
        slog[3][t] = a3 + bv;
    } else if (t >= 96 && t < 100) {
        int c = t - 96;
        float a0 = 0.f, a1 = 0.f, a2 = 0.f, a3 = 0.f;
        #pragma unroll 4
        for (int k = 0; k < FC; k++) {
            float w = Wb[k * 4 + c];
            a0 += sf[0][k] * w;
            a1 += sf[1][k] * w;
            a2 += sf[2][k] * w;
            a3 += sf[3][k] * w;
        }
        float bv = bb[c];
        sdel[0][c] = a0 + bv;
        sdel[1][c] = a1 + bv;
        sdel[2][c] = a2 + bv;
        sdel[3][c] = a3 + bv;
    }
    __syncthreads();

    if (t < 4) {
        int gid = p0 + t;
        float m = -INFINITY;
        for (int c = 0; c <= NUM_CLASSES; c++) m = fmaxf(m, slog[t][c]);
        float s = 0.0f;
        float fg = -INFINITY;
        for (int c = 0; c <= NUM_CLASSES; c++) {
            float e = expf(slog[t][c] - m);
            s += e;
            if (c < NUM_CLASSES) fg = fmaxf(fg, e);
        }
        scores[gid] = fg / s;

        const float* p = prop + (size_t)gid * 4;
        float px1 = p[0], py1 = p[1], px2 = p[2], py2 = p[3];
        float wdt = px2 - px1, hgt = py2 - py1;
        float cx = px1 + 0.5f * wdt, cy = py1 + 0.5f * hgt;
        float dx = sdel[t][0] * 0.1f;
        float dy = sdel[t][1] * 0.1f;
        float dw = fminf(sdel[t][2] * 0.2f, SCALE_CLAMP);
        float dh = fminf(sdel[t][3] * 0.2f, SCALE_CLAMP);
        float pcx = dx * wdt + cx;
        float pcy = dy * hgt + cy;
        float pw = expf(dw) * wdt;
        float ph = expf(dh) * hgt;
        float* ob = boxes + (size_t)gid * 4;
        ob[0] = fminf(fmaxf(pcx - 0.5f * pw, 0.0f), IMG_W);
        ob[1] = fminf(fmaxf(pcy - 0.5f * ph, 0.0f), IMG_H);
        ob[2] = fminf(fmaxf(pcx + 0.5f * pw, 0.0f), IMG_W);
        ob[3] = fminf(fmaxf(pcy + 0.5f * ph, 0.0f), IMG_H);
    }
}

// ---------------------------------------------------------------------------
// Kernel 4: NMS + ranking + det write. grid(2), block(256).
// IoU bitmatrix uses multiply-compare (no FDIV). Greedy runs entirely in
// warp-0 registers: kept words replicated in every lane, each 32-candidate
// word resolved bit-serially with one __ballot_sync per candidate.
// ---------------------------------------------------------------------------
__global__ void nms_kernel(const float* __restrict__ boxes,
                           const float* __restrict__ scores,
                           float* __restrict__ det) {
    int n = blockIdx.x;
    int t = threadIdx.x;

    __shared__ float ss[NR];
    __shared__ int order[NR];
    __shared__ float4 sb[NR];
    __shared__ unsigned int supmask[NR][8];
    __shared__ unsigned int keptw[8];
    __shared__ float smask[NR];

    float s_i = scores[n * NR + t];
    ss[t] = s_i;
    __syncthreads();

    // stable descending rank
    int rk = 0;
    #pragma unroll 8
    for (int j = 0; j < NR; j++) {
        float sj = ss[j];
        rk += (sj > s_i) || (sj == s_i && j < t);
    }
    order[rk] = t;
    __syncthreads();

    sb[t] = ((const float4*)boxes)[n * NR + order[t]];
    __syncthreads();

    // IoU bitmatrix row t (sorted order), multiply-compare
    {
        float4 a = sb[t];
        float aa = (a.z - a.x) * (a.w - a.y);
        #pragma unroll
        for (int w = 0; w < 8; w++) {
            unsigned int word = 0;
            #pragma unroll 4
            for (int k = 0; k < 32; k++) {
                float4 b = sb[w * 32 + k];
                float ba = (b.z - b.x) * (b.w - b.y);
                float lx = fmaxf(a.x, b.x), ly = fmaxf(a.y, b.y);
                float rx = fminf(a.z, b.z), ry = fminf(a.w, b.w);
                float ww = fmaxf(rx - lx, 0.0f), hh = fmaxf(ry - ly, 0.0f);
                float inter = ww * hh;
                float u = fmaxf(aa + ba - inter, 1e-9f);
                if (inter > NMS_TH * u) word |= (1u << k);
            }
            supmask[t][w] = word;
        }
    }
    __syncthreads();

    // register greedy in warp 0
    if (t < 32) {
        unsigned kept[8];
        #pragma unroll
        for (int w = 0; w < 8; w++) kept[w] = 0u;
        #pragma unroll
        for (int w = 0; w < 8; w++) {
            int i = w * 32 + t;
            uint4 q0 = *(const uint4*)&supmask[i][0];
            uint4 q1 = *(const uint4*)&supmask[i][4];
            unsigned rw[8] = {q0.x, q0.y, q0.z, q0.w, q1.x, q1.y, q1.z, q1.w};
            unsigned m = 0;
            #pragma unroll
            for (int w2 = 0; w2 < 8; w2++)
                if (w2 < w) m |= rw[w2] & kept[w2];
            bool sup_prev = (m != 0u);
            unsigned myw = rw[w];
            unsigned kw = 0u;
            #pragma unroll
            for (int k = 0; k < 32; k++) {
                bool keep_me = (!sup_prev) && ((myw & kw) == 0u);
                unsigned b = __ballot_sync(0xffffffffu, keep_me);
                kw |= (b & (1u << k));
            }
            kept[w] = kw;
        }
        #pragma unroll
        for (int w = 0; w < 8; w++)
            if (t == w) keptw[w] = kept[w];
    }
    __syncthreads();

    bool kp = (keptw[rk >> 5] >> (rk & 31)) & 1u;
    kp = kp && (s_i > SCORE_TH);
    smask[t] = kp ? s_i : -INFINITY;
    __syncthreads();

    int rank2 = 0;
    float mi = smask[t];
    #pragma unroll 8
    for (int j = 0; j < NR; j++) {
        float mj = smask[j];
        rank2 += (mj > mi) || (mj == mi && j < t);
    }
    kp = kp && (rank2 < MAX_DET);

    const float* bsrc = boxes + (size_t)(n * NR + t) * 4;
    float* drow = det + (size_t)(n * NR + t) * 6;
    drow[0] = bsrc[0]; drow[1] = bsrc[1];
    drow[2] = bsrc[2]; drow[3] = bsrc[3];
    drow[4] = s_i;
    drow[5] = kp ? 1.0f : 0.0f;
}

// ---------------------------------------------------------------------------
extern "C" void kernel_launch(void* const* d_in, const int* in_sizes, int n_in,
                              void* d_out, int out_size) {
    const float* features = (const float*)d_in[0];
    const float* proposals = (const float*)d_in[1];
    const float* gt_boxes = (const float*)d_in[2];
    // d_in[3] = gt_classes (unused by reference)
    const float* W_cls = (const float*)d_in[4];
    const float* b_cls = (const float*)d_in[5];
    const float* W_box = (const float*)d_in[6];
    const float* b_box = (const float*)d_in[7];

    float* out = (float*)d_out;
    float* det = out;                          // 2*256*6 = 3072
    float* out_idx = out + NIMG * NR * 6;      // 512
    float* out_lbl = out_idx + NIMG * NR;      // 512

    float* featvec; cudaGetSymbolAddress((void**)&featvec, g_featvec);
    float* boxes;   cudaGetSymbolAddress((void**)&boxes, g_boxes);
    float* scores;  cudaGetSymbolAddress((void**)&scores, g_scores);

    const int ROI_SMEM = FH * FW * 8 * (int)sizeof(float);   // 128000 B
    cudaFuncSetAttribute(roi_kernel,
                         cudaFuncAttributeMaxDynamicSharedMemorySize, ROI_SMEM);

    match_kernel<<<NIMG, NR>>>(gt_boxes, proposals, out_idx, out_lbl);
    weight_kernel<<<dim3(8, NIMG), 256>>>(proposals);
    roi_kernel<<<dim3(FC / 8, NIMG), 256, ROI_SMEM>>>(features, featvec);
    head_kernel<<<NIMG * NR / 4, 128>>>(featvec, proposals, W_cls, b_cls,
                                        W_box, b_box, boxes, scores);
    nms_kernel<<<NIMG, NR>>>(boxes, scores, det);
}

// round 5
// speedup vs baseline: 1.3632x; 1.1281x over previous
#include <cuda_runtime.h>
#include <math.h>

#define IMG_H 800.0f
#define IMG_W 1280.0f
#define FSCALE (1.0f/16.0f)
#define PP 14
#define NUM_CLASSES 80
#define SCORE_TH 0.05f
#define NMS_TH 0.5f
#define MAX_DET 100
#define IOU_TH 0.5f
#define SCALE_CLAMP 4.135166556742356f
#define FH 50
#define FW 80
#define FC 1024
#define NIMG 2
#define NR 256
#define NGT 64

// Scratch (device globals; no allocation allowed)
__device__ float g_featvec[NIMG * NR * FC];
__device__ float g_boxes[NIMG * NR * 4];
__device__ float g_scores[NIMG * NR];
__device__ float g_wy[NIMG * NR * FH];
__device__ float g_wx[NIMG * NR * FW];
__device__ int   g_bnd[NIMG * NR * 4];   // ylo,yhi,xlo,xhi

// ---------------------------------------------------------------------------
// Kernel 1: proposal<->gt matching. grid(2), block(256).
// ---------------------------------------------------------------------------
__global__ void match_kernel(const float* __restrict__ gt,
                             const float* __restrict__ prop,
                             float* __restrict__ out_idx,
                             float* __restrict__ out_lbl) {
    int n = blockIdx.x;
    int r = threadIdx.x;
    const float* p = prop + (n * NR + r) * 4;
    float px1 = p[0], py1 = p[1], px2 = p[2], py2 = p[3];
    float pa = (px2 - px1) * (py2 - py1);
    float best = -1.0f;
    int bi = 0;
    for (int g = 0; g < NGT; g++) {
        const float* gb = gt + (n * NGT + g) * 4;
        float gx1 = gb[0], gy1 = gb[1], gx2 = gb[2], gy2 = gb[3];
        float ga = (gx2 - gx1) * (gy2 - gy1);
        float lx = fmaxf(gx1, px1), ly = fmaxf(gy1, py1);
        float rx = fminf(gx2, px2), ry = fminf(gy2, py2);
        float w = fmaxf(rx - lx, 0.0f), h = fmaxf(ry - ly, 0.0f);
        float inter = w * h;
        float iou = inter / fmaxf(ga + pa - inter, 1e-9f);
        if (iou > best) { best = iou; bi = g; }
    }
    out_idx[n * NR + r] = (float)bi;
    out_lbl[n * NR + r] = (best >= IOU_TH) ? 1.0f : 0.0f;
}

// ---------------------------------------------------------------------------
// Kernel 1b: separable ROIAlign weight tables per box -> global.
// ---------------------------------------------------------------------------
__global__ void weight_kernel(const float* __restrict__ prop) {
    int n = blockIdx.y;
    int b0 = blockIdx.x * 32;
    int t = threadIdx.x;

    __shared__ float wy[32 * FH];
    __shared__ float wx[32 * FW];

    for (int i = t; i < 32 * FH; i += 256) wy[i] = 0.0f;
    for (int i = t; i < 32 * FW; i += 256) wx[i] = 0.0f;
    __syncthreads();

    int b = t >> 3;          // box within block
    int sub = t & 7;
    int box = b0 + b;
    const float* p = prop + (n * NR + box) * 4;

    if (sub == 0) {
        float y1 = p[1] * FSCALE, y2 = p[3] * FSCALE;
        float bh = (y2 - y1) * (1.0f / (float)PP);
        int lo = FH, hi = 0;
        for (int py = 0; py < PP; py++) {
            float gy = y1 + ((float)py + 0.5f) * bh - 0.5f;
            gy = fminf(fmaxf(gy, 0.0f), (float)(FH - 1));
            float y0 = floorf(gy);
            int y0i = (int)y0;
            int y1i = min(y0i + 1, FH - 1);
            float ly = gy - y0;
            wy[b * FH + y0i] += 1.0f - ly;
            wy[b * FH + y1i] += ly;
            lo = min(lo, y0i);
            hi = max(hi, y1i);
        }
        g_bnd[(n * NR + box) * 4 + 0] = lo;
        g_bnd[(n * NR + box) * 4 + 1] = hi;
    } else if (sub == 1) {
        float x1 = p[0] * FSCALE, x2 = p[2] * FSCALE;
        float bw = (x2 - x1) * (1.0f / (float)PP);
        int lo = FW, hi = 0;
        for (int px = 0; px < PP; px++) {
            float gx = x1 + ((float)px + 0.5f) * bw - 0.5f;
            gx = fminf(fmaxf(gx, 0.0f), (float)(FW - 1));
            float x0 = floorf(gx);
            int x0i = (int)x0;
            int x1i = min(x0i + 1, FW - 1);
            float lx = gx - x0;
            wx[b * FW + x0i] += 1.0f - lx;
            wx[b * FW + x1i] += lx;
            lo = min(lo, x0i);
            hi = max(hi, x1i);
        }
        g_bnd[(n * NR + box) * 4 + 2] = lo;
        g_bnd[(n * NR + box) * 4 + 3] = hi;
    }
    __syncthreads();

    for (int i = t; i < 32 * FH; i += 256) g_wy[(n * NR + b0) * FH + i] = wy[i];
    for (int i = t; i < 32 * FW; i += 256) g_wx[(n * NR + b0) * FW + i] = wx[i];
}

// ---------------------------------------------------------------------------
// Kernel 2: ROIAlign via shared feature slice.
// grid(FC/8=128, 2), block(256), dyn smem 125KB. Feature traffic = 33MB total.
// ---------------------------------------------------------------------------
__global__ void roi_kernel(const float* __restrict__ feat,
                           float* __restrict__ featvec) {
    extern __shared__ float sl[];           // [FH*FW][8]
    int c0 = blockIdx.x * 8;
    int n = blockIdx.y;
    int t = threadIdx.x;

    const float* fbase = feat + (size_t)n * FH * FW * FC + c0;
    for (int idx = t; idx < FH * FW; idx += 256) {
        const float4* src = (const float4*)(fbase + (size_t)idx * FC);
        float4 a = src[0];
        float4 b = src[1];
        float4* dst = (float4*)(sl + idx * 8);
        dst[0] = a;
        dst[1] = b;
    }
    __syncthreads();

    int box = t;
    const int4 bnd = *(const int4*)&g_bnd[(n * NR + box) * 4];
    int ylo = bnd.x, yhi = bnd.y, xlo = bnd.z, xhi = bnd.w;
    const float* wyp = &g_wy[(n * NR + box) * FH];
    const float* wxp = &g_wx[(n * NR + box) * FW];

    float4 acc0 = make_float4(0.f, 0.f, 0.f, 0.f);
    float4 acc1 = make_float4(0.f, 0.f, 0.f, 0.f);

    for (int y = ylo; y <= yhi; y++) {
        float wyv = wyp[y];
        const float* rowp = sl + (y * FW) * 8;
        for (int x = xlo; x <= xhi; x++) {
            float w = wyv * wxp[x];
            const float4* cell = (const float4*)(rowp + x * 8);
            float4 v0 = cell[0];
            float4 v1 = cell[1];
            acc0.x += w * v0.x; acc0.y += w * v0.y;
            acc0.z += w * v0.z; acc0.w += w * v0.w;
            acc1.x += w * v1.x; acc1.y += w * v1.y;
            acc1.z += w * v1.z; acc1.w += w * v1.w;
        }
    }
    const float inv = 1.0f / (float)(PP * PP);
    acc0.x *= inv; acc0.y *= inv; acc0.z *= inv; acc0.w *= inv;
    acc1.x *= inv; acc1.y *= inv; acc1.z *= inv; acc1.w *= inv;
    float4* out = (float4*)(featvec + (size_t)(n * NR + box) * FC + c0);
    out[0] = acc0;
    out[1] = acc1;
}

// ---------------------------------------------------------------------------
// Kernel 3: heads. grid(256): 2 proposals per block, block(384).
// Thread layout: c = t%96 (column), kq = t/96 (K-quarter of 256).
// Cols 0..80 = cls logits, cols 88..91 = box deltas. Each thread accumulates
// 2 proposals over its K-slice (unroll 8 -> MLP 8); partials reduced in smem.
// 12 warps/block, 256 blocks -> ~20 warps/SM; W traffic halved to ~85MB.
// ---------------------------------------------------------------------------
__global__ void head_kernel(const float* __restrict__ featvec,
                            const float* __restrict__ prop,
                            const float* __restrict__ Wc,
                            const float* __restrict__ bc,
                            const float* __restrict__ Wb,
                            const float* __restrict__ bb,
                            float* __restrict__ boxes,
                            float* __restrict__ scores) {
    int p0 = blockIdx.x * 2;
    int t = threadIdx.x;
    int c = t % 96;
    int kq = t / 96;

    __shared__ float sf[2][FC];
    __shared__ float part[4][2][96];
    __shared__ float slog[2][NUM_CLASSES + 1];
    __shared__ float sdel[2][4];

    const float* fv = featvec + (size_t)p0 * FC;
    for (int i = t; i < 2 * FC; i += 384) sf[i >> 10][i & (FC - 1)] = fv[i];
    __syncthreads();

    float a0 = 0.f, a1 = 0.f;
    int kbeg = kq * 256;
    if (c < NUM_CLASSES + 1) {
        const float* w = Wc + c + (size_t)kbeg * (NUM_CLASSES + 1);
        #pragma unroll 8
        for (int k = 0; k < 256; k++) {
            float wv = w[k * (NUM_CLASSES + 1)];
            a0 += sf[0][kbeg + k] * wv;
            a1 += sf[1][kbeg + k] * wv;
        }
    } else if (c >= 88 && c < 92) {
        int cc = c - 88;
        const float* w = Wb + cc + (size_t)kbeg * 4;
        #pragma unroll 8
        for (int k = 0; k < 256; k++) {
            float wv = w[k * 4];
            a0 += sf[0][kbeg + k] * wv;
            a1 += sf[1][kbeg + k] * wv;
        }
    }
    part[kq][0][c] = a0;
    part[kq][1][c] = a1;
    __syncthreads();

    if (t < 96) {
        float s0 = part[0][0][t] + part[1][0][t] + part[2][0][t] + part[3][0][t];
        float s1 = part[0][1][t] + part[1][1][t] + part[2][1][t] + part[3][1][t];
        if (t < NUM_CLASSES + 1) {
            float bv = bc[t];
            slog[0][t] = s0 + bv;
            slog[1][t] = s1 + bv;
        } else if (t >= 88 && t < 92) {
            float bv = bb[t - 88];
            sdel[0][t - 88] = s0 + bv;
            sdel[1][t - 88] = s1 + bv;
        }
    }
    __syncthreads();

    if (t < 2) {
        int gid = p0 + t;
        float m = -INFINITY;
        for (int cc = 0; cc <= NUM_CLASSES; cc++) m = fmaxf(m, slog[t][cc]);
        float s = 0.0f;
        float fg = -INFINITY;
        for (int cc = 0; cc <= NUM_CLASSES; cc++) {
            float e = expf(slog[t][cc] - m);
            s += e;
            if (cc < NUM_CLASSES) fg = fmaxf(fg, e);
        }
        scores[gid] = fg / s;

        const float* p = prop + (size_t)gid * 4;
        float px1 = p[0], py1 = p[1], px2 = p[2], py2 = p[3];
        float wdt = px2 - px1, hgt = py2 - py1;
        float cx = px1 + 0.5f * wdt, cy = py1 + 0.5f * hgt;
        float dx = sdel[t][0] * 0.1f;
        float dy = sdel[t][1] * 0.1f;
        float dw = fminf(sdel[t][2] * 0.2f, SCALE_CLAMP);
        float dh = fminf(sdel[t][3] * 0.2f, SCALE_CLAMP);
        float pcx = dx * wdt + cx;
        float pcy = dy * hgt + cy;
        float pw = expf(dw) * wdt;
        float ph = expf(dh) * hgt;
        float* ob = boxes + (size_t)gid * 4;
        ob[0] = fminf(fmaxf(pcx - 0.5f * pw, 0.0f), IMG_W);
        ob[1] = fminf(fmaxf(pcy - 0.5f * ph, 0.0f), IMG_H);
        ob[2] = fminf(fmaxf(pcx + 0.5f * pw, 0.0f), IMG_W);
        ob[3] = fminf(fmaxf(pcy + 0.5f * ph, 0.0f), IMG_H);
    }
}

// ---------------------------------------------------------------------------
// Kernel 4: NMS + ranking + det write. grid(2), block(256).
// ---------------------------------------------------------------------------
__global__ void nms_kernel(const float* __restrict__ boxes,
                           const float* __restrict__ scores,
                           float* __restrict__ det) {
    int n = blockIdx.x;
    int t = threadIdx.x;

    __shared__ float ss[NR];
    __shared__ int order[NR];
    __shared__ float4 sb[NR];
    __shared__ unsigned int supmask[NR][8];
    __shared__ unsigned int keptw[8];
    __shared__ float smask[NR];

    float s_i = scores[n * NR + t];
    ss[t] = s_i;
    __syncthreads();

    int rk = 0;
    #pragma unroll 8
    for (int j = 0; j < NR; j++) {
        float sj = ss[j];
        rk += (sj > s_i) || (sj == s_i && j < t);
    }
    order[rk] = t;
    __syncthreads();

    sb[t] = ((const float4*)boxes)[n * NR + order[t]];
    __syncthreads();

    {
        float4 a = sb[t];
        float aa = (a.z - a.x) * (a.w - a.y);
        #pragma unroll
        for (int w = 0; w < 8; w++) {
            unsigned int word = 0;
            #pragma unroll 4
            for (int k = 0; k < 32; k++) {
                float4 b = sb[w * 32 + k];
                float ba = (b.z - b.x) * (b.w - b.y);
                float lx = fmaxf(a.x, b.x), ly = fmaxf(a.y, b.y);
                float rx = fminf(a.z, b.z), ry = fminf(a.w, b.w);
                float ww = fmaxf(rx - lx, 0.0f), hh = fmaxf(ry - ly, 0.0f);
                float inter = ww * hh;
                float u = fmaxf(aa + ba - inter, 1e-9f);
                if (inter > NMS_TH * u) word |= (1u << k);
            }
            supmask[t][w] = word;
        }
    }
    __syncthreads();

    if (t < 32) {
        unsigned kept[8];
        #pragma unroll
        for (int w = 0; w < 8; w++) kept[w] = 0u;
        #pragma unroll
        for (int w = 0; w < 8; w++) {
            int i = w * 32 + t;
            uint4 q0 = *(const uint4*)&supmask[i][0];
            uint4 q1 = *(const uint4*)&supmask[i][4];
            unsigned rw[8] = {q0.x, q0.y, q0.z, q0.w, q1.x, q1.y, q1.z, q1.w};
            unsigned m = 0;
            #pragma unroll
            for (int w2 = 0; w2 < 8; w2++)
                if (w2 < w) m |= rw[w2] & kept[w2];
            bool sup_prev = (m != 0u);
            unsigned myw = rw[w];
            unsigned kw = 0u;
            #pragma unroll
            for (int k = 0; k < 32; k++) {
                bool keep_me = (!sup_prev) && ((myw & kw) == 0u);
                unsigned b = __ballot_sync(0xffffffffu, keep_me);
                kw |= (b & (1u << k));
            }
            kept[w] = kw;
        }
        #pragma unroll
        for (int w = 0; w < 8; w++)
            if (t == w) keptw[w] = kept[w];
    }
    __syncthreads();

    bool kp = (keptw[rk >> 5] >> (rk & 31)) & 1u;
    kp = kp && (s_i > SCORE_TH);
    smask[t] = kp ? s_i : -INFINITY;
    __syncthreads();

    int rank2 = 0;
    float mi = smask[t];
    #pragma unroll 8
    for (int j = 0; j < NR; j++) {
        float mj = smask[j];
        rank2 += (mj > mi) || (mj == mi && j < t);
    }
    kp = kp && (rank2 < MAX_DET);

    const float* bsrc = boxes + (size_t)(n * NR + t) * 4;
    float* drow = det + (size_t)(n * NR + t) * 6;
    drow[0] = bsrc[0]; drow[1] = bsrc[1];
    drow[2] = bsrc[2]; drow[3] = bsrc[3];
    drow[4] = s_i;
    drow[5] = kp ? 1.0f : 0.0f;
}

// ---------------------------------------------------------------------------
extern "C" void kernel_launch(void* const* d_in, const int* in_sizes, int n_in,
                              void* d_out, int out_size) {
    const float* features = (const float*)d_in[0];
    const float* proposals = (const float*)d_in[1];
    const float* gt_boxes = (const float*)d_in[2];
    // d_in[3] = gt_classes (unused by reference)
    const float* W_cls = (const float*)d_in[4];
    const float* b_cls = (const float*)d_in[5];
    const float* W_box = (const float*)d_in[6];
    const float* b_box = (const float*)d_in[7];

    float* out = (float*)d_out;
    float* det = out;                          // 2*256*6 = 3072
    float* out_idx = out + NIMG * NR * 6;      // 512
    float* out_lbl = out_idx + NIMG * NR;      // 512

    float* featvec; cudaGetSymbolAddress((void**)&featvec, g_featvec);
    float* boxes;   cudaGetSymbolAddress((void**)&boxes, g_boxes);
    float* scores;  cudaGetSymbolAddress((void**)&scores, g_scores);

    const int ROI_SMEM = FH * FW * 8 * (int)sizeof(float);   // 128000 B
    cudaFuncSetAttribute(roi_kernel,
                         cudaFuncAttributeMaxDynamicSharedMemorySize, ROI_SMEM);

    match_kernel<<<NIMG, NR>>>(gt_boxes, proposals, out_idx, out_lbl);
    weight_kernel<<<dim3(8, NIMG), 256>>>(proposals);
    roi_kernel<<<dim3(FC / 8, NIMG), 256, ROI_SMEM>>>(features, featvec);
    head_kernel<<<NIMG * NR / 2, 384>>>(featvec, proposals, W_cls, b_cls,
                                        W_box, b_box, boxes, scores);
    nms_kernel<<<NIMG, NR>>>(boxes, scores, det);
}

// round 6
// speedup vs baseline: 1.5600x; 1.1443x over previous
#include <cuda_runtime.h>
#include <math.h>

#define IMG_H 800.0f
#define IMG_W 1280.0f
#define FSCALE (1.0f/16.0f)
#define PP 14
#define NUM_CLASSES 80
#define SCORE_TH 0.05f
#define NMS_TH 0.5f
#define MAX_DET 100
#define IOU_TH 0.5f
#define SCALE_CLAMP 4.135166556742356f
#define FH 50
#define FW 80
#define FC 1024
#define NIMG 2
#define NR 256
#define NGT 64
#define NPROP (NIMG * NR)          // 512
#define NCOL 96                    // padded output cols: 0..80 cls, 81..84 box
#define KSPLIT 8
#define KSLICE (FC / KSPLIT)       // 128
#define MTILE 32

// Scratch (device globals; no allocation allowed)
__device__ float g_featvec[NPROP * FC];
__device__ float g_boxes[NPROP * 4];
__device__ float g_scores[NPROP];
__device__ float g_wy[NPROP * FH];
__device__ float g_wx[NPROP * FW];
__device__ int   g_bnd[NPROP * 4];               // ylo,yhi,xlo,xhi
__device__ float g_part[KSPLIT * NPROP * NCOL];  // split-K partials

// ---------------------------------------------------------------------------
// Kernel 1: fused match + separable ROIAlign weight tables.
// grid(8, 2): 32 boxes per block, block(256). Per box: sub 0 = y-table,
// sub 1 = x-table, sub 2 = GT matching (all independent).
// ---------------------------------------------------------------------------
__global__ void weight_kernel(const float* __restrict__ prop,
                              const float* __restrict__ gt,
                              float* __restrict__ out_idx,
                              float* __restrict__ out_lbl) {
    int n = blockIdx.y;
    int b0 = blockIdx.x * 32;
    int t = threadIdx.x;

    __shared__ float wy[32 * FH];
    __shared__ float wx[32 * FW];

    for (int i = t; i < 32 * FH; i += 256) wy[i] = 0.0f;
    for (int i = t; i < 32 * FW; i += 256) wx[i] = 0.0f;
    __syncthreads();

    int b = t >> 3;          // box within block
    int sub = t & 7;
    int box = b0 + b;
    const float* p = prop + (n * NR + box) * 4;

    if (sub == 0) {
        float y1 = p[1] * FSCALE, y2 = p[3] * FSCALE;
        float bh = (y2 - y1) * (1.0f / (float)PP);
        int lo = FH, hi = 0;
        for (int py = 0; py < PP; py++) {
            float gy = y1 + ((float)py + 0.5f) * bh - 0.5f;
            gy = fminf(fmaxf(gy, 0.0f), (float)(FH - 1));
            float y0 = floorf(gy);
            int y0i = (int)y0;
            int y1i = min(y0i + 1, FH - 1);
            float ly = gy - y0;
            wy[b * FH + y0i] += 1.0f - ly;
            wy[b * FH + y1i] += ly;
            lo = min(lo, y0i);
            hi = max(hi, y1i);
        }
        g_bnd[(n * NR + box) * 4 + 0] = lo;
        g_bnd[(n * NR + box) * 4 + 1] = hi;
    } else if (sub == 1) {
        float x1 = p[0] * FSCALE, x2 = p[2] * FSCALE;
        float bw = (x2 - x1) * (1.0f / (float)PP);
        int lo = FW, hi = 0;
        for (int px = 0; px < PP; px++) {
            float gx = x1 + ((float)px + 0.5f) * bw - 0.5f;
            gx = fminf(fmaxf(gx, 0.0f), (float)(FW - 1));
            float x0 = floorf(gx);
            int x0i = (int)x0;
            int x1i = min(x0i + 1, FW - 1);
            float lx = gx - x0;
            wx[b * FW + x0i] += 1.0f - lx;
            wx[b * FW + x1i] += lx;
            lo = min(lo, x0i);
            hi = max(hi, x1i);
        }
        g_bnd[(n * NR + box) * 4 + 2] = lo;
        g_bnd[(n * NR + box) * 4 + 3] = hi;
    } else if (sub == 2) {
        float px1 = p[0], py1 = p[1], px2 = p[2], py2 = p[3];
        float pa = (px2 - px1) * (py2 - py1);
        float best = -1.0f;
        int bi = 0;
        for (int g = 0; g < NGT; g++) {
            const float* gb = gt + (n * NGT + g) * 4;
            float gx1 = gb[0], gy1 = gb[1], gx2 = gb[2], gy2 = gb[3];
            float ga = (gx2 - gx1) * (gy2 - gy1);
            float lx = fmaxf(gx1, px1), ly = fmaxf(gy1, py1);
            float rx = fminf(gx2, px2), ry = fminf(gy2, py2);
            float w = fmaxf(rx - lx, 0.0f), h = fmaxf(ry - ly, 0.0f);
            float inter = w * h;
            float iou = inter / fmaxf(ga + pa - inter, 1e-9f);
            if (iou > best) { best = iou; bi = g; }
        }
        out_idx[n * NR + box] = (float)bi;
        out_lbl[n * NR + box] = (best >= IOU_TH) ? 1.0f : 0.0f;
    }
    __syncthreads();

    for (int i = t; i < 32 * FH; i += 256) g_wy[(n * NR + b0) * FH + i] = wy[i];
    for (int i = t; i < 32 * FW; i += 256) g_wx[(n * NR + b0) * FW + i] = wx[i];
}

// ---------------------------------------------------------------------------
// Kernel 2: ROIAlign via shared feature slice.
// grid(FC/8=128, 2), block(256), dyn smem 125KB. Feature traffic = 33MB total.
// ---------------------------------------------------------------------------
__global__ void roi_kernel(const float* __restrict__ feat,
                           float* __restrict__ featvec) {
    extern __shared__ float sl[];           // [FH*FW][8]
    int c0 = blockIdx.x * 8;
    int n = blockIdx.y;
    int t = threadIdx.x;

    const float* fbase = feat + (size_t)n * FH * FW * FC + c0;
    for (int idx = t; idx < FH * FW; idx += 256) {
        const float4* src = (const float4*)(fbase + (size_t)idx * FC);
        float4 a = src[0];
        float4 b = src[1];
        float4* dst = (float4*)(sl + idx * 8);
        dst[0] = a;
        dst[1] = b;
    }
    __syncthreads();

    int box = t;
    const int4 bnd = *(const int4*)&g_bnd[(n * NR + box) * 4];
    int ylo = bnd.x, yhi = bnd.y, xlo = bnd.z, xhi = bnd.w;
    const float* wyp = &g_wy[(n * NR + box) * FH];
    const float* wxp = &g_wx[(n * NR + box) * FW];

    float4 acc0 = make_float4(0.f, 0.f, 0.f, 0.f);
    float4 acc1 = make_float4(0.f, 0.f, 0.f, 0.f);

    for (int y = ylo; y <= yhi; y++) {
        float wyv = wyp[y];
        const float* rowp = sl + (y * FW) * 8;
        for (int x = xlo; x <= xhi; x++) {
            float w = wyv * wxp[x];
            const float4* cell = (const float4*)(rowp + x * 8);
            float4 v0 = cell[0];
            float4 v1 = cell[1];
            acc0.x += w * v0.x; acc0.y += w * v0.y;
            acc0.z += w * v0.z; acc0.w += w * v0.w;
            acc1.x += w * v1.x; acc1.y += w * v1.y;
            acc1.z += w * v1.z; acc1.w += w * v1.w;
        }
    }
    const float inv = 1.0f / (float)(PP * PP);
    acc0.x *= inv; acc0.y *= inv; acc0.z *= inv; acc0.w *= inv;
    acc1.x *= inv; acc1.y *= inv; acc1.z *= inv; acc1.w *= inv;
    float4* out = (float4*)(featvec + (size_t)(n * NR + box) * FC + c0);
    out[0] = acc0;
    out[1] = acc1;
}

// ---------------------------------------------------------------------------
// Kernel 3a: head GEMM, smem-tiled + split-K.
// grid(16, 8) = (M-tile of 32 props, K-slice of 128), block(256), 64KB smem.
// smem: sf tile [32][128], W tile [128][96] (cols 0..80 = W_cls, 81..84 =
// W_box, rest zero). Thread (colg = t%32, propg = t/32) computes a 4-prop x
// 3-col register tile: per k 7 conflict-free LDS feed 12 FMA.
// ---------------------------------------------------------------------------
__global__ void gemm_kernel(const float* __restrict__ featvec,
                            const float* __restrict__ Wc,
                            const float* __restrict__ Wb) {
    extern __shared__ float sm[];
    float* sfS = sm;                 // 32*128
    float* wS = sm + MTILE * KSLICE; // 128*96

    int t = threadIdx.x;
    int p0 = blockIdx.x * MTILE;
    int k0 = blockIdx.y * KSLICE;

    // load sf tile (coalesced over k)
    for (int i = t; i < MTILE * KSLICE; i += 256) {
        int p = i >> 7;          // /128
        int k = i & (KSLICE - 1);
        sfS[i] = featvec[(size_t)(p0 + p) * FC + k0 + k];
    }
    // load fused W tile (coalesced over cols)
    for (int i = t; i < KSLICE * NCOL; i += 256) {
        int r = i / NCOL;
        int c = i - r * NCOL;
        float v = 0.0f;
        if (c < NUM_CLASSES + 1) v = Wc[(size_t)(k0 + r) * (NUM_CLASSES + 1) + c];
        else if (c < NUM_CLASSES + 5) v = Wb[(size_t)(k0 + r) * 4 + (c - 81)];
        wS[i] = v;
    }
    __syncthreads();

    int colg = t & 31;
    int propg = t >> 5;              // 0..7
    const float* sfp = sfS + (propg * 4) * KSLICE;

    float a00 = 0.f, a01 = 0.f, a02 = 0.f;
    float a10 = 0.f, a11 = 0.f, a12 = 0.f;
    float a20 = 0.f, a21 = 0.f, a22 = 0.f;
    float a30 = 0.f, a31 = 0.f, a32 = 0.f;

    #pragma unroll 4
    for (int k = 0; k < KSLICE; k++) {
        float w0 = wS[k * NCOL + colg];
        float w1 = wS[k * NCOL + colg + 32];
        float w2 = wS[k * NCOL + colg + 64];
        float s0 = sfp[k];
        float s1 = sfp[KSLICE + k];
        float s2 = sfp[2 * KSLICE + k];
        float s3 = sfp[3 * KSLICE + k];
        a00 += s0 * w0; a01 += s0 * w1; a02 += s0 * w2;
        a10 += s1 * w0; a11 += s1 * w1; a12 += s1 * w2;
        a20 += s2 * w0; a21 += s2 * w1; a22 += s2 * w2;
        a30 += s3 * w0; a31 += s3 * w1; a32 += s3 * w2;
    }

    float* op = g_part + (size_t)blockIdx.y * NPROP * NCOL +
                (size_t)(p0 + propg * 4) * NCOL + colg;
    op[0] = a00; op[32] = a01; op[64] = a02;
    op += NCOL; op[0] = a10; op[32] = a11; op[64] = a12;
    op += NCOL; op[0] = a20; op[32] = a21; op[64] = a22;
    op += NCOL; op[0] = a30; op[32] = a31; op[64] = a32;
}

// ---------------------------------------------------------------------------
// Kernel 3b: reduce split-K partials + bias, softmax fg score, box decode.
// grid(512) one block per proposal, block(96).
// ---------------------------------------------------------------------------
__global__ void reduce_kernel(const float* __restrict__ prop,
                              const float* __restrict__ bc,
                              const float* __restrict__ bb,
                              float* __restrict__ boxes,
                              float* __restrict__ scores) {
    int gid = blockIdx.x;
    int t = threadIdx.x;
    __shared__ float slog[NUM_CLASSES + 5];

    if (t < NUM_CLASSES + 5) {
        float s = 0.0f;
        #pragma unroll
        for (int ks = 0; ks < KSPLIT; ks++)
            s += g_part[(size_t)ks * NPROP * NCOL + (size_t)gid * NCOL + t];
        if (t < NUM_CLASSES + 1) s += bc[t];
        else s += bb[t - 81];
        slog[t] = s;
    }
    __syncthreads();

    if (t == 0) {
        float m = -INFINITY;
        for (int c = 0; c <= NUM_CLASSES; c++) m = fmaxf(m, slog[c]);
        float ssum = 0.0f;
        float fg = -INFINITY;
        for (int c = 0; c <= NUM_CLASSES; c++) {
            float e = expf(slog[c] - m);
            ssum += e;
            if (c < NUM_CLASSES) fg = fmaxf(fg, e);
        }
        scores[gid] = fg / ssum;

        const float* p = prop + (size_t)gid * 4;
        float px1 = p[0], py1 = p[1], px2 = p[2], py2 = p[3];
        float wdt = px2 - px1, hgt = py2 - py1;
        float cx = px1 + 0.5f * wdt, cy = py1 + 0.5f * hgt;
        float dx = slog[81] * 0.1f;
        float dy = slog[82] * 0.1f;
        float dw = fminf(slog[83] * 0.2f, SCALE_CLAMP);
        float dh = fminf(slog[84] * 0.2f, SCALE_CLAMP);
        float pcx = dx * wdt + cx;
        float pcy = dy * hgt + cy;
        float pw = expf(dw) * wdt;
        float ph = expf(dh) * hgt;
        float* ob = boxes + (size_t)gid * 4;
        ob[0] = fminf(fmaxf(pcx - 0.5f * pw, 0.0f), IMG_W);
        ob[1] = fminf(fmaxf(pcy - 0.5f * ph, 0.0f), IMG_H);
        ob[2] = fminf(fmaxf(pcx + 0.5f * pw, 0.0f), IMG_W);
        ob[3] = fminf(fmaxf(pcy + 0.5f * ph, 0.0f), IMG_H);
    }
}

// ---------------------------------------------------------------------------
// Kernel 4: NMS + ranking + det write. grid(2), block(256).
// ---------------------------------------------------------------------------
__global__ void nms_kernel(const float* __restrict__ boxes,
                           const float* __restrict__ scores,
                           float* __restrict__ det) {
    int n = blockIdx.x;
    int t = threadIdx.x;

    __shared__ float ss[NR];
    __shared__ int order[NR];
    __shared__ float4 sb[NR];
    __shared__ unsigned int supmask[NR][8];
    __shared__ unsigned int keptw[8];
    __shared__ float smask[NR];

    float s_i = scores[n * NR + t];
    ss[t] = s_i;
    __syncthreads();

    int rk = 0;
    #pragma unroll 8
    for (int j = 0; j < NR; j++) {
        float sj = ss[j];
        rk += (sj > s_i) || (sj == s_i && j < t);
    }
    order[rk] = t;
    __syncthreads();

    sb[t] = ((const float4*)boxes)[n * NR + order[t]];
    __syncthreads();

    {
        float4 a = sb[t];
        float aa = (a.z - a.x) * (a.w - a.y);
        #pragma unroll
        for (int w = 0; w < 8; w++) {
            unsigned int word = 0;
            #pragma unroll 4
            for (int k = 0; k < 32; k++) {
                float4 b = sb[w * 32 + k];
                float ba = (b.z - b.x) * (b.w - b.y);
                float lx = fmaxf(a.x, b.x), ly = fmaxf(a.y, b.y);
                float rx = fminf(a.z, b.z), ry = fminf(a.w, b.w);
                float ww = fmaxf(rx - lx, 0.0f), hh = fmaxf(ry - ly, 0.0f);
                float inter = ww * hh;
                float u = fmaxf(aa + ba - inter, 1e-9f);
                if (inter > NMS_TH * u) word |= (1u << k);
            }
            supmask[t][w] = word;
        }
    }
    __syncthreads();

    if (t < 32) {
        unsigned kept[8];
        #pragma unroll
        for (int w = 0; w < 8; w++) kept[w] = 0u;
        #pragma unroll
        for (int w = 0; w < 8; w++) {
            int i = w * 32 + t;
            uint4 q0 = *(const uint4*)&supmask[i][0];
            uint4 q1 = *(const uint4*)&supmask[i][4];
            unsigned rw[8] = {q0.x, q0.y, q0.z, q0.w, q1.x, q1.y, q1.z, q1.w};
            unsigned m = 0;
            #pragma unroll
            for (int w2 = 0; w2 < 8; w2++)
                if (w2 < w) m |= rw[w2] & kept[w2];
            bool sup_prev = (m != 0u);
            unsigned myw = rw[w];
            unsigned kw = 0u;
            #pragma unroll
            for (int k = 0; k < 32; k++) {
                bool keep_me = (!sup_prev) && ((myw & kw) == 0u);
                unsigned b = __ballot_sync(0xffffffffu, keep_me);
                kw |= (b & (1u << k));
            }
            kept[w] = kw;
        }
        #pragma unroll
        for (int w = 0; w < 8; w++)
            if (t == w) keptw[w] = kept[w];
    }
    __syncthreads();

    bool kp = (keptw[rk >> 5] >> (rk & 31)) & 1u;
    kp = kp && (s_i > SCORE_TH);
    smask[t] = kp ? s_i : -INFINITY;
    __syncthreads();

    int rank2 = 0;
    float mi = smask[t];
    #pragma unroll 8
    for (int j = 0; j < NR; j++) {
        float mj = smask[j];
        rank2 += (mj > mi) || (mj == mi && j < t);
    }
    kp = kp && (rank2 < MAX_DET);

    const float* bsrc = boxes + (size_t)(n * NR + t) * 4;
    float* drow = det + (size_t)(n * NR + t) * 6;
    drow[0] = bsrc[0]; drow[1] = bsrc[1];
    drow[2] = bsrc[2]; drow[3] = bsrc[3];
    drow[4] = s_i;
    drow[5] = kp ? 1.0f : 0.0f;
}

// ---------------------------------------------------------------------------
extern "C" void kernel_launch(void* const* d_in, const int* in_sizes, int n_in,
                              void* d_out, int out_size) {
    const float* features = (const float*)d_in[0];
    const float* proposals = (const float*)d_in[1];
    const float* gt_boxes = (const float*)d_in[2];
    // d_in[3] = gt_classes (unused by reference)
    const float* W_cls = (const float*)d_in[4];
    const float* b_cls = (const float*)d_in[5];
    const float* W_box = (const float*)d_in[6];
    const float* b_box = (const float*)d_in[7];

    float* out = (float*)d_out;
    float* det = out;                          // 2*256*6 = 3072
    float* out_idx = out + NIMG * NR * 6;      // 512
    float* out_lbl = out_idx + NIMG * NR;      // 512

    float* featvec; cudaGetSymbolAddress((void**)&featvec, g_featvec);
    float* boxes;   cudaGetSymbolAddress((void**)&boxes, g_boxes);
    float* scores;  cudaGetSymbolAddress((void**)&scores, g_scores);

    const int ROI_SMEM = FH * FW * 8 * (int)sizeof(float);         // 128000 B
    const int GEMM_SMEM = (MTILE * KSLICE + KSLICE * NCOL) * 4;    // 65536 B
    cudaFuncSetAttribute(roi_kernel,
                         cudaFuncAttributeMaxDynamicSharedMemorySize, ROI_SMEM);
    cudaFuncSetAttribute(gemm_kernel,
                         cudaFuncAttributeMaxDynamicSharedMemorySize, GEMM_SMEM);

    weight_kernel<<<dim3(8, NIMG), 256>>>(proposals, gt_boxes, out_idx, out_lbl);
    roi_kernel<<<dim3(FC / 8, NIMG), 256, ROI_SMEM>>>(features, featvec);
    gemm_kernel<<<dim3(NPROP / MTILE, KSPLIT), 256, GEMM_SMEM>>>(featvec,
                                                                 W_cls, W_box);
    reduce_kernel<<<NPROP, 96>>>(proposals, b_cls, b_box, boxes, scores);
    nms_kernel<<<NIMG, NR>>>(boxes, scores, det);
}